// round 1
// baseline (speedup 1.0000x reference)
#include <cuda_runtime.h>
#include <math.h>

#define NN 100000
#define EE 3200000
#define FIN 500
#define HD 64
#define NCLS 40
#define NL 8

// ---------------- scratch (device globals; no allocation allowed) ----------------
__device__ float g_h0[NN * HD];
__device__ float g_h [NN * HD];
__device__ float g_hi[NN * HD];
__device__ int   g_rowptr[NN + 1];
__device__ int   g_off[NN];
__device__ int   g_cnt[NN];
__device__ int   g_blksum[128];
__device__ int   g_blkoff[128];
__device__ int   g_ccol[EE];
__device__ float g_cw[EE];

// ---------------- CSR build ----------------
__global__ void k_zero_cnt() {
    int i = blockIdx.x * blockDim.x + threadIdx.x;
    if (i < NN) g_cnt[i] = 0;
}

__global__ void k_count(const int* __restrict__ row) {
    int e = blockIdx.x * blockDim.x + threadIdx.x;
    if (e < EE) atomicAdd(&g_cnt[row[e]], 1);
}

__global__ void k_scan1() {
    __shared__ int s[1024];
    int i = blockIdx.x * 1024 + threadIdx.x;
    int v = (i < NN) ? g_cnt[i] : 0;
    s[threadIdx.x] = v;
    __syncthreads();
    #pragma unroll
    for (int off = 1; off < 1024; off <<= 1) {
        int t = (threadIdx.x >= off) ? s[threadIdx.x - off] : 0;
        __syncthreads();
        s[threadIdx.x] += t;
        __syncthreads();
    }
    if (i < NN) g_rowptr[i] = s[threadIdx.x] - v;   // exclusive within block
    if (threadIdx.x == 1023) g_blksum[blockIdx.x] = s[1023];
}

__global__ void k_scan2(int nb) {
    if (threadIdx.x == 0 && blockIdx.x == 0) {
        int acc = 0;
        for (int b = 0; b < nb; b++) { g_blkoff[b] = acc; acc += g_blksum[b]; }
    }
}

__global__ void k_scan3() {
    int i = blockIdx.x * blockDim.x + threadIdx.x;
    if (i < NN) {
        int v = g_rowptr[i] + g_blkoff[i >> 10];
        g_rowptr[i] = v;
        g_off[i] = v;
    }
    if (i == 0) g_rowptr[NN] = EE;
}

__global__ void k_scatter(const int* __restrict__ row, const int* __restrict__ col,
                          const float* __restrict__ w) {
    int e = blockIdx.x * blockDim.x + threadIdx.x;
    if (e < EE) {
        int r = row[e];
        int p = atomicAdd(&g_off[r], 1);
        g_ccol[p] = col[e];
        g_cw[p]   = w[e];
    }
}

// ---------------- input GEMM: h0 = relu(x @ W_in + b_in) ----------------
// block: 256 threads, 64-row tile, full 64 cols; thread = (rl = tid/4, cg = tid%4) -> 16 cols
__global__ void k_gemm_in(const float* __restrict__ x, const float* __restrict__ W,
                          const float* __restrict__ b) {
    __shared__ float sx[64][33];
    __shared__ float sw[32][64];
    int rowBase = blockIdx.x * 64;
    int tid = threadIdx.x;
    int rl = tid >> 2;
    int cg = tid & 3;
    float acc[16];
    #pragma unroll
    for (int c = 0; c < 16; c++) acc[c] = 0.f;

    for (int k0 = 0; k0 < FIN; k0 += 32) {
        #pragma unroll
        for (int j = 0; j < 8; j++) {              // 2048 x-elements
            int i = tid + j * 256;
            int r = i >> 5, kk = i & 31;
            int gr = rowBase + r, gk = k0 + kk;
            sx[r][kk] = (gr < NN && gk < FIN) ? x[gr * FIN + gk] : 0.f;
        }
        #pragma unroll
        for (int j = 0; j < 8; j++) {              // 2048 W-elements
            int i = tid + j * 256;
            int kk = i >> 6, c = i & 63;
            int gk = k0 + kk;
            sw[kk][c] = (gk < FIN) ? W[gk * HD + c] : 0.f;
        }
        __syncthreads();
        #pragma unroll
        for (int kk = 0; kk < 32; kk++) {
            float a = sx[rl][kk];
            const float4* wp = reinterpret_cast<const float4*>(&sw[kk][cg << 4]);
            #pragma unroll
            for (int q = 0; q < 4; q++) {
                float4 w4 = wp[q];
                acc[4 * q + 0] += a * w4.x;
                acc[4 * q + 1] += a * w4.y;
                acc[4 * q + 2] += a * w4.z;
                acc[4 * q + 3] += a * w4.w;
            }
        }
        __syncthreads();
    }
    int gr = rowBase + rl;
    if (gr < NN) {
        #pragma unroll
        for (int q = 0; q < 4; q++) {
            float4 o;
            o.x = fmaxf(acc[4 * q + 0] + b[(cg << 4) + 4 * q + 0], 0.f);
            o.y = fmaxf(acc[4 * q + 1] + b[(cg << 4) + 4 * q + 1], 0.f);
            o.z = fmaxf(acc[4 * q + 2] + b[(cg << 4) + 4 * q + 2], 0.f);
            o.w = fmaxf(acc[4 * q + 3] + b[(cg << 4) + 4 * q + 3], 0.f);
            *reinterpret_cast<float4*>(&g_h0[gr * HD + (cg << 4) + 4 * q]) = o;
        }
    }
}

// ---------------- SpMM: hi[r] = sum_{e in row r} w_e * hin[col_e] ----------------
// 16 threads per destination row, each owns 4 consecutive floats (float4)
__global__ void k_spmm(int first) {
    const float* __restrict__ hin = first ? g_h0 : g_h;
    int tid = blockIdx.x * blockDim.x + threadIdx.x;
    int r = tid >> 4;
    if (r >= NN) return;
    int lg = tid & 15;
    int s = g_rowptr[r], e = g_rowptr[r + 1];
    float4 acc = make_float4(0.f, 0.f, 0.f, 0.f);
    for (int i = s; i < e; i++) {
        int   c = __ldg(&g_ccol[i]);
        float w = __ldg(&g_cw[i]);
        float4 hv = *reinterpret_cast<const float4*>(&hin[c * HD + (lg << 2)]);
        acc.x += w * hv.x;
        acc.y += w * hv.y;
        acc.z += w * hv.z;
        acc.w += w * hv.w;
    }
    *reinterpret_cast<float4*>(&g_hi[r * HD + (lg << 2)]) = acc;
}

// ---------------- per-layer combine: h = relu(beta*(support@Wl) + (1-beta)*support)
//                  support = 0.9*hi + 0.1*h0
__global__ void k_combine(const float* __restrict__ Wl, float beta) {
    __shared__ float sW[64][64];
    __shared__ float sS[64][65];
    int rowBase = blockIdx.x * 64;
    int tid = threadIdx.x;
    #pragma unroll
    for (int j = 0; j < 16; j++) {
        int i = tid + j * 256;
        sW[i >> 6][i & 63] = Wl[i];
    }
    #pragma unroll
    for (int j = 0; j < 16; j++) {
        int i = tid + j * 256;
        int rl = i >> 6, c = i & 63;
        int gr = rowBase + rl;
        float v = 0.f;
        if (gr < NN) {
            int g = gr * HD + c;
            v = 0.9f * g_hi[g] + 0.1f * g_h0[g];
        }
        sS[rl][c] = v;
    }
    __syncthreads();
    int rl = tid >> 2, cg = tid & 3;
    float acc[16];
    #pragma unroll
    for (int c = 0; c < 16; c++) acc[c] = 0.f;
    #pragma unroll 8
    for (int k = 0; k < 64; k++) {
        float a = sS[rl][k];
        const float4* wp = reinterpret_cast<const float4*>(&sW[k][cg << 4]);
        #pragma unroll
        for (int q = 0; q < 4; q++) {
            float4 w4 = wp[q];
            acc[4 * q + 0] += a * w4.x;
            acc[4 * q + 1] += a * w4.y;
            acc[4 * q + 2] += a * w4.z;
            acc[4 * q + 3] += a * w4.w;
        }
    }
    int gr = rowBase + rl;
    if (gr < NN) {
        float ob = 1.f - beta;
        #pragma unroll
        for (int q = 0; q < 4; q++) {
            float4 o;
            o.x = fmaxf(beta * acc[4 * q + 0] + ob * sS[rl][(cg << 4) + 4 * q + 0], 0.f);
            o.y = fmaxf(beta * acc[4 * q + 1] + ob * sS[rl][(cg << 4) + 4 * q + 1], 0.f);
            o.z = fmaxf(beta * acc[4 * q + 2] + ob * sS[rl][(cg << 4) + 4 * q + 2], 0.f);
            o.w = fmaxf(beta * acc[4 * q + 3] + ob * sS[rl][(cg << 4) + 4 * q + 3], 0.f);
            *reinterpret_cast<float4*>(&g_h[gr * HD + (cg << 4) + 4 * q]) = o;
        }
    }
}

// ---------------- output: log_softmax(h @ W_out + b_out) ----------------
// one warp per row; lane covers col=lane (0..31) and col=lane+32 (lanes 0..7)
__global__ void k_out(const float* __restrict__ Wout, const float* __restrict__ bout,
                      float* __restrict__ out) {
    __shared__ float sW[HD * NCLS];
    __shared__ float sb[NCLS];
    __shared__ float srow[8][64];
    int tid = threadIdx.x;
    for (int i = tid; i < HD * NCLS; i += 256) sW[i] = Wout[i];
    if (tid < NCLS) sb[tid] = bout[tid];
    __syncthreads();
    int wid = tid >> 5, lane = tid & 31;
    int r = blockIdx.x * 8 + wid;
    if (r >= NN) return;
    srow[wid][lane]      = g_h[r * HD + lane];
    srow[wid][lane + 32] = g_h[r * HD + lane + 32];
    __syncwarp();
    int c2 = (lane & 7) + 32;
    float a0 = sb[lane];
    float a1 = sb[c2];
    #pragma unroll 8
    for (int k = 0; k < HD; k++) {
        float hk = srow[wid][k];
        a0 += hk * sW[k * NCLS + lane];
        a1 += hk * sW[k * NCLS + c2];
    }
    bool has2 = (lane < 8);
    float m = fmaxf(a0, has2 ? a1 : -INFINITY);
    #pragma unroll
    for (int o = 16; o; o >>= 1) m = fmaxf(m, __shfl_xor_sync(0xFFFFFFFFu, m, o));
    float s = __expf(a0 - m) + (has2 ? __expf(a1 - m) : 0.f);
    #pragma unroll
    for (int o = 16; o; o >>= 1) s += __shfl_xor_sync(0xFFFFFFFFu, s, o);
    float lse = m + __logf(s);
    out[r * NCLS + lane] = a0 - lse;
    if (has2) out[r * NCLS + c2] = a1 - lse;
}

// ---------------- launch ----------------
extern "C" void kernel_launch(void* const* d_in, const int* in_sizes, int n_in,
                              void* d_out, int out_size) {
    const float* x      = (const float*)d_in[0];
    const int*   row    = (const int*)  d_in[1];
    const int*   col    = (const int*)  d_in[2];
    const float* ew     = (const float*)d_in[3];
    const float* W_in   = (const float*)d_in[4];
    const float* b_in   = (const float*)d_in[5];
    const float* conv_W = (const float*)d_in[6];
    const float* W_out  = (const float*)d_in[7];
    const float* b_out  = (const float*)d_in[8];
    float* out = (float*)d_out;

    // CSR build (once per replay; reused by all 8 layers)
    k_zero_cnt<<<(NN + 255) / 256, 256>>>();
    k_count   <<<(EE + 255) / 256, 256>>>(row);
    int nb = (NN + 1023) / 1024;
    k_scan1  <<<nb, 1024>>>();
    k_scan2  <<<1, 32>>>(nb);
    k_scan3  <<<(NN + 255) / 256, 256>>>();
    k_scatter<<<(EE + 255) / 256, 256>>>(row, col, ew);

    // input projection
    k_gemm_in<<<(NN + 63) / 64, 256>>>(x, W_in, b_in);

    // 8 GCNII layers
    for (int l = 0; l < NL; l++) {
        float beta = logf(0.5f / (float)(l + 1) + 1.0f);
        k_spmm   <<<(NN * 16 + 255) / 256, 256>>>(l == 0 ? 1 : 0);
        k_combine<<<(NN + 63) / 64, 256>>>(conv_W + l * HD * HD, beta);
    }

    // output head + log_softmax
    k_out<<<(NN + 7) / 8, 256>>>(W_out, b_out, out);
}

// round 2
// speedup vs baseline: 1.5121x; 1.5121x over previous
#include <cuda_runtime.h>
#include <math.h>

#define NN 100000
#define EE 3200000
#define FIN 500
#define HD 64
#define NCLS 40
#define NL 8

// ---------------- scratch (device globals; no allocation allowed) ----------------
__device__ float g_h0[NN * HD];
__device__ float g_h [NN * HD];
__device__ float g_hi[NN * HD];   // holds support S after spmm
__device__ int   g_rowptr[NN + 1];
__device__ int   g_off[NN];
__device__ int   g_cnt[NN];
__device__ int   g_blksum[128];
__device__ int   g_blkoff[128];
__device__ int   g_ccol[EE];
__device__ float g_cw[EE];
__device__ float g_M[NL * HD * HD];   // M_l = beta*W_l + (1-beta)*I

// ---------------- packed f32x2 helpers ----------------
#define FMA2(acc, a, b) \
    asm("fma.rn.f32x2 %0, %1, %2, %0;" : "+l"(acc) : "l"(a), "l"(b))

__device__ __forceinline__ unsigned long long pack2(float x, float y) {
    unsigned long long r;
    asm("mov.b64 %0, {%1, %2};" : "=l"(r) : "f"(x), "f"(y));
    return r;
}
__device__ __forceinline__ void unpack2(unsigned long long v, float& x, float& y) {
    asm("mov.b64 {%0, %1}, %2;" : "=f"(x), "=f"(y) : "l"(v));
}

// ---------------- CSR build ----------------
__global__ void k_zero_cnt() {
    int i = blockIdx.x * blockDim.x + threadIdx.x;
    if (i < NN) g_cnt[i] = 0;
}

__global__ void k_count(const int* __restrict__ row) {
    int e = blockIdx.x * blockDim.x + threadIdx.x;
    if (e < EE) atomicAdd(&g_cnt[row[e]], 1);
}

__global__ void k_scan1() {
    __shared__ int s[1024];
    int i = blockIdx.x * 1024 + threadIdx.x;
    int v = (i < NN) ? g_cnt[i] : 0;
    s[threadIdx.x] = v;
    __syncthreads();
    #pragma unroll
    for (int off = 1; off < 1024; off <<= 1) {
        int t = (threadIdx.x >= off) ? s[threadIdx.x - off] : 0;
        __syncthreads();
        s[threadIdx.x] += t;
        __syncthreads();
    }
    if (i < NN) g_rowptr[i] = s[threadIdx.x] - v;
    if (threadIdx.x == 1023) g_blksum[blockIdx.x] = s[1023];
}

__global__ void k_scan2(int nb) {
    if (threadIdx.x == 0 && blockIdx.x == 0) {
        int acc = 0;
        for (int b = 0; b < nb; b++) { g_blkoff[b] = acc; acc += g_blksum[b]; }
    }
}

__global__ void k_scan3() {
    int i = blockIdx.x * blockDim.x + threadIdx.x;
    if (i < NN) {
        int v = g_rowptr[i] + g_blkoff[i >> 10];
        g_rowptr[i] = v;
        g_off[i] = v;
    }
    if (i == 0) g_rowptr[NN] = EE;
}

__global__ void k_scatter(const int* __restrict__ row, const int* __restrict__ col,
                          const float* __restrict__ w) {
    int e = blockIdx.x * blockDim.x + threadIdx.x;
    if (e < EE) {
        int r = row[e];
        int p = atomicAdd(&g_off[r], 1);
        g_ccol[p] = col[e];
        g_cw[p]   = w[e];
    }
}

// ---------------- M_l = beta*W_l + (1-beta)*I ----------------
__global__ void k_make_M(const float* __restrict__ conv_W) {
    int l = blockIdx.x;
    float beta = logf(0.5f / (float)(l + 1) + 1.0f);
    float ob = 1.0f - beta;
    #pragma unroll
    for (int j = 0; j < 16; j++) {
        int idx = threadIdx.x + j * 256;
        int r = idx >> 6, c = idx & 63;
        float v = beta * conv_W[l * HD * HD + idx];
        if (r == c) v += ob;
        g_M[l * HD * HD + idx] = v;
    }
}

// ---------------- input GEMM: h0 = relu(x @ W_in + b_in) ----------------
// 128-row tile, 64 cols; thread = (rl = tid/4 -> rows rl, rl+64; cg = tid%4 -> 16 cols)
__global__ void k_gemm_in(const float* __restrict__ x, const float* __restrict__ W,
                          const float* __restrict__ b) {
    __shared__ __align__(16) float sx[128][33];
    __shared__ __align__(16) float sw[32][64];
    int rowBase = blockIdx.x * 128;
    int tid = threadIdx.x;
    int rl = tid >> 2;
    int cg = tid & 3;
    unsigned long long acc0[8], acc1[8];
    unsigned long long z = pack2(0.f, 0.f);
    #pragma unroll
    for (int c = 0; c < 8; c++) { acc0[c] = z; acc1[c] = z; }

    for (int k0 = 0; k0 < FIN; k0 += 32) {
        #pragma unroll
        for (int j = 0; j < 16; j++) {              // 4096 x-elements
            int i = tid + j * 256;
            int r = i >> 5, kk = i & 31;
            int gr = rowBase + r, gk = k0 + kk;
            sx[r][kk] = (gr < NN && gk < FIN) ? x[gr * FIN + gk] : 0.f;
        }
        #pragma unroll
        for (int j = 0; j < 8; j++) {               // 2048 W-elements
            int i = tid + j * 256;
            int kk = i >> 6, c = i & 63;
            int gk = k0 + kk;
            sw[kk][c] = (gk < FIN) ? W[gk * HD + c] : 0.f;
        }
        __syncthreads();
        #pragma unroll
        for (int kk = 0; kk < 32; kk++) {
            float a0 = sx[rl][kk];
            float a1 = sx[rl + 64][kk];
            unsigned long long aa0 = pack2(a0, a0);
            unsigned long long aa1 = pack2(a1, a1);
            #pragma unroll
            for (int q = 0; q < 4; q++) {
                ulonglong2 w2 = *reinterpret_cast<const ulonglong2*>(&sw[kk][(cg << 4) + (q << 2)]);
                FMA2(acc0[2 * q + 0], aa0, w2.x);
                FMA2(acc0[2 * q + 1], aa0, w2.y);
                FMA2(acc1[2 * q + 0], aa1, w2.x);
                FMA2(acc1[2 * q + 1], aa1, w2.y);
            }
        }
        __syncthreads();
    }
    #pragma unroll
    for (int half = 0; half < 2; half++) {
        int gr = rowBase + rl + half * 64;
        if (gr < NN) {
            unsigned long long* acc = half ? acc1 : acc0;
            #pragma unroll
            for (int q = 0; q < 4; q++) {
                float4 o;
                float e0, e1, e2, e3;
                unpack2(acc[2 * q + 0], e0, e1);
                unpack2(acc[2 * q + 1], e2, e3);
                int cb = (cg << 4) + (q << 2);
                o.x = fmaxf(e0 + b[cb + 0], 0.f);
                o.y = fmaxf(e1 + b[cb + 1], 0.f);
                o.z = fmaxf(e2 + b[cb + 2], 0.f);
                o.w = fmaxf(e3 + b[cb + 3], 0.f);
                *reinterpret_cast<float4*>(&g_h0[gr * HD + cb]) = o;
            }
        }
    }
}

// ---------------- SpMM + residual: S[r] = 0.9 * sum_e w_e*hin[col_e] + 0.1*h0[r] ----
// 16 threads per destination row, each owns 4 consecutive floats; unroll 4 for MLP
__global__ void k_spmm(int first) {
    const float* __restrict__ hin = first ? g_h0 : g_h;
    int tid = blockIdx.x * blockDim.x + threadIdx.x;
    int r = tid >> 4;
    if (r >= NN) return;
    int lg = (tid & 15) << 2;
    int s = g_rowptr[r], e = g_rowptr[r + 1];
    float4 acc = make_float4(0.f, 0.f, 0.f, 0.f);
    int i = s;
    for (; i + 4 <= e; i += 4) {
        int   c0 = __ldg(&g_ccol[i + 0]);
        int   c1 = __ldg(&g_ccol[i + 1]);
        int   c2 = __ldg(&g_ccol[i + 2]);
        int   c3 = __ldg(&g_ccol[i + 3]);
        float w0 = __ldg(&g_cw[i + 0]);
        float w1 = __ldg(&g_cw[i + 1]);
        float w2 = __ldg(&g_cw[i + 2]);
        float w3 = __ldg(&g_cw[i + 3]);
        float4 v0 = *reinterpret_cast<const float4*>(&hin[c0 * HD + lg]);
        float4 v1 = *reinterpret_cast<const float4*>(&hin[c1 * HD + lg]);
        float4 v2 = *reinterpret_cast<const float4*>(&hin[c2 * HD + lg]);
        float4 v3 = *reinterpret_cast<const float4*>(&hin[c3 * HD + lg]);
        acc.x += w0 * v0.x; acc.y += w0 * v0.y; acc.z += w0 * v0.z; acc.w += w0 * v0.w;
        acc.x += w1 * v1.x; acc.y += w1 * v1.y; acc.z += w1 * v1.z; acc.w += w1 * v1.w;
        acc.x += w2 * v2.x; acc.y += w2 * v2.y; acc.z += w2 * v2.z; acc.w += w2 * v2.w;
        acc.x += w3 * v3.x; acc.y += w3 * v3.y; acc.z += w3 * v3.z; acc.w += w3 * v3.w;
    }
    for (; i < e; i++) {
        int   c = __ldg(&g_ccol[i]);
        float w = __ldg(&g_cw[i]);
        float4 hv = *reinterpret_cast<const float4*>(&hin[c * HD + lg]);
        acc.x += w * hv.x; acc.y += w * hv.y; acc.z += w * hv.z; acc.w += w * hv.w;
    }
    float4 h0v = *reinterpret_cast<const float4*>(&g_h0[r * HD + lg]);
    acc.x = 0.9f * acc.x + 0.1f * h0v.x;
    acc.y = 0.9f * acc.y + 0.1f * h0v.y;
    acc.z = 0.9f * acc.z + 0.1f * h0v.z;
    acc.w = 0.9f * acc.w + 0.1f * h0v.w;
    *reinterpret_cast<float4*>(&g_hi[r * HD + lg]) = acc;
}

// ---------------- per-layer combine: h = relu(S @ M_l) ----------------
// 128-row tile; thread = (rl rows rl, rl+64; cg -> 16 cols)
__global__ void k_combine(int layer) {
    __shared__ __align__(16) float sW[64][64];
    __shared__ __align__(16) float sS[128][68];
    const float* __restrict__ Ml = &g_M[layer * HD * HD];
    int rowBase = blockIdx.x * 128;
    int tid = threadIdx.x;
    #pragma unroll
    for (int j = 0; j < 16; j++) {
        int i = tid + j * 256;
        sW[i >> 6][i & 63] = Ml[i];
    }
    #pragma unroll
    for (int j = 0; j < 8; j++) {                  // 2048 float4 = 8192 floats
        int i = tid + j * 256;
        int rl = i >> 4, c = (i & 15) << 2;
        int gr = rowBase + rl;
        float4 v = make_float4(0.f, 0.f, 0.f, 0.f);
        if (gr < NN) v = *reinterpret_cast<const float4*>(&g_hi[gr * HD + c]);
        *reinterpret_cast<float4*>(&sS[rl][c]) = v;
    }
    __syncthreads();
    int rl = tid >> 2, cg = tid & 3;
    unsigned long long acc0[8], acc1[8];
    unsigned long long z = pack2(0.f, 0.f);
    #pragma unroll
    for (int c = 0; c < 8; c++) { acc0[c] = z; acc1[c] = z; }
    #pragma unroll 8
    for (int k = 0; k < 64; k++) {
        float a0 = sS[rl][k];
        float a1 = sS[rl + 64][k];
        unsigned long long aa0 = pack2(a0, a0);
        unsigned long long aa1 = pack2(a1, a1);
        #pragma unroll
        for (int q = 0; q < 4; q++) {
            ulonglong2 w2 = *reinterpret_cast<const ulonglong2*>(&sW[k][(cg << 4) + (q << 2)]);
            FMA2(acc0[2 * q + 0], aa0, w2.x);
            FMA2(acc0[2 * q + 1], aa0, w2.y);
            FMA2(acc1[2 * q + 0], aa1, w2.x);
            FMA2(acc1[2 * q + 1], aa1, w2.y);
        }
    }
    #pragma unroll
    for (int half = 0; half < 2; half++) {
        int gr = rowBase + rl + half * 64;
        if (gr < NN) {
            unsigned long long* acc = half ? acc1 : acc0;
            #pragma unroll
            for (int q = 0; q < 4; q++) {
                float e0, e1, e2, e3;
                unpack2(acc[2 * q + 0], e0, e1);
                unpack2(acc[2 * q + 1], e2, e3);
                float4 o;
                o.x = fmaxf(e0, 0.f);
                o.y = fmaxf(e1, 0.f);
                o.z = fmaxf(e2, 0.f);
                o.w = fmaxf(e3, 0.f);
                *reinterpret_cast<float4*>(&g_h[gr * HD + (cg << 4) + (q << 2)]) = o;
            }
        }
    }
}

// ---------------- output: log_softmax(h @ W_out + b_out) ----------------
__global__ void k_out(const float* __restrict__ Wout, const float* __restrict__ bout,
                      float* __restrict__ out) {
    __shared__ float sW[HD * NCLS];
    __shared__ float sb[NCLS];
    __shared__ float srow[8][64];
    int tid = threadIdx.x;
    for (int i = tid; i < HD * NCLS; i += 256) sW[i] = Wout[i];
    if (tid < NCLS) sb[tid] = bout[tid];
    __syncthreads();
    int wid = tid >> 5, lane = tid & 31;
    int r = blockIdx.x * 8 + wid;
    if (r >= NN) return;
    srow[wid][lane]      = g_h[r * HD + lane];
    srow[wid][lane + 32] = g_h[r * HD + lane + 32];
    __syncwarp();
    int c2 = (lane & 7) + 32;
    float a0 = sb[lane];
    float a1 = sb[c2];
    #pragma unroll 8
    for (int k = 0; k < HD; k++) {
        float hk = srow[wid][k];
        a0 += hk * sW[k * NCLS + lane];
        a1 += hk * sW[k * NCLS + c2];
    }
    bool has2 = (lane < 8);
    float m = fmaxf(a0, has2 ? a1 : -INFINITY);
    #pragma unroll
    for (int o = 16; o; o >>= 1) m = fmaxf(m, __shfl_xor_sync(0xFFFFFFFFu, m, o));
    float s = __expf(a0 - m) + (has2 ? __expf(a1 - m) : 0.f);
    #pragma unroll
    for (int o = 16; o; o >>= 1) s += __shfl_xor_sync(0xFFFFFFFFu, s, o);
    float lse = m + __logf(s);
    out[r * NCLS + lane] = a0 - lse;
    if (has2) out[r * NCLS + c2] = a1 - lse;
}

// ---------------- launch ----------------
extern "C" void kernel_launch(void* const* d_in, const int* in_sizes, int n_in,
                              void* d_out, int out_size) {
    const float* x      = (const float*)d_in[0];
    const int*   row    = (const int*)  d_in[1];
    const int*   col    = (const int*)  d_in[2];
    const float* ew     = (const float*)d_in[3];
    const float* W_in   = (const float*)d_in[4];
    const float* b_in   = (const float*)d_in[5];
    const float* conv_W = (const float*)d_in[6];
    const float* W_out  = (const float*)d_in[7];
    const float* b_out  = (const float*)d_in[8];
    float* out = (float*)d_out;

    // CSR build
    k_zero_cnt<<<(NN + 255) / 256, 256>>>();
    k_count   <<<(EE + 255) / 256, 256>>>(row);
    int nb = (NN + 1023) / 1024;
    k_scan1  <<<nb, 1024>>>();
    k_scan2  <<<1, 32>>>(nb);
    k_scan3  <<<(NN + 255) / 256, 256>>>();
    k_scatter<<<(EE + 255) / 256, 256>>>(row, col, ew);

    // per-layer combined matrices
    k_make_M<<<NL, 256>>>(conv_W);

    // input projection
    k_gemm_in<<<(NN + 127) / 128, 256>>>(x, W_in, b_in);

    // 8 GCNII layers
    for (int l = 0; l < NL; l++) {
        k_spmm   <<<(NN * 16 + 255) / 256, 256>>>(l == 0 ? 1 : 0);
        k_combine<<<(NN + 127) / 128, 256>>>(l);
    }

    // output head + log_softmax
    k_out<<<(NN + 7) / 8, 256>>>(W_out, b_out, out);
}

// round 4
// speedup vs baseline: 1.5230x; 1.0073x over previous
#include <cuda_runtime.h>
#include <math.h>

#define NN 100000
#define EE 3200000
#define FIN 500
#define HD 64
#define NCLS 40
#define NL 8

// ---------------- scratch (device globals; no allocation allowed) ----------------
__device__ float g_h0[NN * HD];
__device__ float g_h [NN * HD];
__device__ float g_hi[NN * HD];   // holds support S after spmm
__device__ int   g_rowptr[NN + 1];
__device__ int   g_off[NN];
__device__ int   g_cnt[NN];
__device__ int   g_blksum[128];
__device__ int   g_blkoff[128];
__device__ int2  g_cpack[EE];     // packed (col, weight-as-int)
__device__ float g_M[NL * HD * HD];   // M_l = beta*W_l + (1-beta)*I

// ---------------- packed f32x2 helpers ----------------
#define FMA2(acc, a, b) \
    asm("fma.rn.f32x2 %0, %1, %2, %0;" : "+l"(acc) : "l"(a), "l"(b))

__device__ __forceinline__ unsigned long long pack2(float x, float y) {
    unsigned long long r;
    asm("mov.b64 %0, {%1, %2};" : "=l"(r) : "f"(x), "f"(y));
    return r;
}
__device__ __forceinline__ void unpack2(unsigned long long v, float& x, float& y) {
    asm("mov.b64 {%0, %1}, %2;" : "=f"(x), "=f"(y) : "l"(v));
}

// ---------------- CSR build ----------------
__global__ void k_zero_cnt() {
    int i = blockIdx.x * blockDim.x + threadIdx.x;
    if (i < NN) g_cnt[i] = 0;
}

__global__ void k_count(const int* __restrict__ row) {
    int e = blockIdx.x * blockDim.x + threadIdx.x;
    if (e < EE) atomicAdd(&g_cnt[row[e]], 1);
}

__global__ void k_scan1() {
    __shared__ int s[1024];
    int i = blockIdx.x * 1024 + threadIdx.x;
    int v = (i < NN) ? g_cnt[i] : 0;
    s[threadIdx.x] = v;
    __syncthreads();
    #pragma unroll
    for (int off = 1; off < 1024; off <<= 1) {
        int t = (threadIdx.x >= off) ? s[threadIdx.x - off] : 0;
        __syncthreads();
        s[threadIdx.x] += t;
        __syncthreads();
    }
    if (i < NN) g_rowptr[i] = s[threadIdx.x] - v;
    if (threadIdx.x == 1023) g_blksum[blockIdx.x] = s[1023];
}

__global__ void k_scan2(int nb) {
    if (threadIdx.x == 0 && blockIdx.x == 0) {
        int acc = 0;
        for (int b = 0; b < nb; b++) { g_blkoff[b] = acc; acc += g_blksum[b]; }
    }
}

__global__ void k_scan3() {
    int i = blockIdx.x * blockDim.x + threadIdx.x;
    if (i < NN) {
        int v = g_rowptr[i] + g_blkoff[i >> 10];
        g_rowptr[i] = v;
        g_off[i] = v;
    }
    if (i == 0) g_rowptr[NN] = EE;
}

__global__ void k_scatter(const int* __restrict__ row, const int* __restrict__ col,
                          const float* __restrict__ w) {
    int e = blockIdx.x * blockDim.x + threadIdx.x;
    if (e < EE) {
        int r = row[e];
        int p = atomicAdd(&g_off[r], 1);
        g_cpack[p] = make_int2(col[e], __float_as_int(w[e]));
    }
}

// ---------------- M_l = beta*W_l + (1-beta)*I ----------------
__global__ void k_make_M(const float* __restrict__ conv_W) {
    int l = blockIdx.x;
    float beta = logf(0.5f / (float)(l + 1) + 1.0f);
    float ob = 1.0f - beta;
    #pragma unroll
    for (int j = 0; j < 16; j++) {
        int idx = threadIdx.x + j * 256;
        int r = idx >> 6, c = idx & 63;
        float v = beta * conv_W[l * HD * HD + idx];
        if (r == c) v += ob;
        g_M[l * HD * HD + idx] = v;
    }
}

// ---------------- input GEMM: h0 = relu(x @ W_in + b_in) ----------------
// 128-row tile, 64 cols; thread = (rl = tid/4 -> rows rl, rl+64; cg = tid%4 -> 16 cols)
__global__ void k_gemm_in(const float* __restrict__ x, const float* __restrict__ W,
                          const float* __restrict__ b) {
    __shared__ __align__(16) float sx[128][36];
    __shared__ __align__(16) float sw[32][64];
    int rowBase = blockIdx.x * 128;
    int tid = threadIdx.x;
    int rl = tid >> 2;
    int cg = tid & 3;
    unsigned long long acc0[8], acc1[8];
    unsigned long long z = pack2(0.f, 0.f);
    #pragma unroll
    for (int c = 0; c < 8; c++) { acc0[c] = z; acc1[c] = z; }

    for (int k0 = 0; k0 < FIN; k0 += 32) {
        // 128 rows x 8 float4 = 1024 float4; 4 per thread
        #pragma unroll
        for (int j = 0; j < 4; j++) {
            int i = tid + j * 256;
            int r = i >> 3, kk4 = i & 7;
            int gr = rowBase + r;
            int gk = k0 + (kk4 << 2);
            float4 v = make_float4(0.f, 0.f, 0.f, 0.f);
            if (gr < NN && gk < FIN)
                v = *reinterpret_cast<const float4*>(&x[gr * FIN + gk]);
            *reinterpret_cast<float4*>(&sx[r][kk4 << 2]) = v;
        }
        // 32 k x 64 cols = 512 float4; 2 per thread
        #pragma unroll
        for (int j = 0; j < 2; j++) {
            int i = tid + j * 256;
            int kk = i >> 4, c4 = (i & 15) << 2;
            int gk = k0 + kk;
            float4 v = make_float4(0.f, 0.f, 0.f, 0.f);
            if (gk < FIN)
                v = *reinterpret_cast<const float4*>(&W[gk * HD + c4]);
            *reinterpret_cast<float4*>(&sw[kk][c4]) = v;
        }
        __syncthreads();
        #pragma unroll
        for (int kk = 0; kk < 32; kk++) {
            float a0 = sx[rl][kk];
            float a1 = sx[rl + 64][kk];
            unsigned long long aa0 = pack2(a0, a0);
            unsigned long long aa1 = pack2(a1, a1);
            #pragma unroll
            for (int q = 0; q < 4; q++) {
                ulonglong2 w2 = *reinterpret_cast<const ulonglong2*>(&sw[kk][(cg << 4) + (q << 2)]);
                FMA2(acc0[2 * q + 0], aa0, w2.x);
                FMA2(acc0[2 * q + 1], aa0, w2.y);
                FMA2(acc1[2 * q + 0], aa1, w2.x);
                FMA2(acc1[2 * q + 1], aa1, w2.y);
            }
        }
        __syncthreads();
    }
    #pragma unroll
    for (int half = 0; half < 2; half++) {
        int gr = rowBase + rl + half * 64;
        if (gr < NN) {
            unsigned long long* acc = half ? acc1 : acc0;
            #pragma unroll
            for (int q = 0; q < 4; q++) {
                float4 o;
                float e0, e1, e2, e3;
                unpack2(acc[2 * q + 0], e0, e1);
                unpack2(acc[2 * q + 1], e2, e3);
                int cb = (cg << 4) + (q << 2);
                o.x = fmaxf(e0 + b[cb + 0], 0.f);
                o.y = fmaxf(e1 + b[cb + 1], 0.f);
                o.z = fmaxf(e2 + b[cb + 2], 0.f);
                o.w = fmaxf(e3 + b[cb + 3], 0.f);
                *reinterpret_cast<float4*>(&g_h0[gr * HD + cb]) = o;
            }
        }
    }
}

// ---------------- SpMM + residual: S[r] = 0.9 * sum_e w_e*hin[col_e] + 0.1*h0[r] ----
// 16 threads per destination row, each owns 4 consecutive floats; unroll 8 for MLP
__global__ void k_spmm(int first) {
    const float* __restrict__ hin = first ? g_h0 : g_h;
    int tid = blockIdx.x * blockDim.x + threadIdx.x;
    int r = tid >> 4;
    if (r >= NN) return;
    int lg = (tid & 15) << 2;
    int s = g_rowptr[r], e = g_rowptr[r + 1];
    float4 acc = make_float4(0.f, 0.f, 0.f, 0.f);
    int i = s;
    #pragma unroll 1
    for (; i + 8 <= e; i += 8) {
        int2 p[8];
        #pragma unroll
        for (int j = 0; j < 8; j++) p[j] = __ldg(&g_cpack[i + j]);
        float4 v[8];
        #pragma unroll
        for (int j = 0; j < 8; j++)
            v[j] = *reinterpret_cast<const float4*>(&hin[p[j].x * HD + lg]);
        #pragma unroll
        for (int j = 0; j < 8; j++) {
            float w = __int_as_float(p[j].y);
            acc.x += w * v[j].x;
            acc.y += w * v[j].y;
            acc.z += w * v[j].z;
            acc.w += w * v[j].w;
        }
    }
    for (; i < e; i++) {
        int2 p = __ldg(&g_cpack[i]);
        float w = __int_as_float(p.y);
        float4 hv = *reinterpret_cast<const float4*>(&hin[p.x * HD + lg]);
        acc.x += w * hv.x; acc.y += w * hv.y; acc.z += w * hv.z; acc.w += w * hv.w;
    }
    float4 h0v = *reinterpret_cast<const float4*>(&g_h0[r * HD + lg]);
    acc.x = 0.9f * acc.x + 0.1f * h0v.x;
    acc.y = 0.9f * acc.y + 0.1f * h0v.y;
    acc.z = 0.9f * acc.z + 0.1f * h0v.z;
    acc.w = 0.9f * acc.w + 0.1f * h0v.w;
    *reinterpret_cast<float4*>(&g_hi[r * HD + lg]) = acc;
}

// ---------------- per-layer combine: h = relu(S @ M_l) ----------------
__global__ void k_combine(int layer) {
    __shared__ __align__(16) float sW[64][64];
    __shared__ __align__(16) float sS[128][68];
    const float* __restrict__ Ml = &g_M[layer * HD * HD];
    int rowBase = blockIdx.x * 128;
    int tid = threadIdx.x;
    #pragma unroll
    for (int j = 0; j < 4; j++) {
        int i = tid + j * 256;
        int kk = i >> 4, c4 = (i & 15) << 2;
        *reinterpret_cast<float4*>(&sW[kk][c4]) =
            *reinterpret_cast<const float4*>(&Ml[kk * HD + c4]);
    }
    #pragma unroll
    for (int j = 0; j < 8; j++) {
        int i = tid + j * 256;
        int rl = i >> 4, c = (i & 15) << 2;
        int gr = rowBase + rl;
        float4 v = make_float4(0.f, 0.f, 0.f, 0.f);
        if (gr < NN) v = *reinterpret_cast<const float4*>(&g_hi[gr * HD + c]);
        *reinterpret_cast<float4*>(&sS[rl][c]) = v;
    }
    __syncthreads();
    int rl = tid >> 2, cg = tid & 3;
    unsigned long long acc0[8], acc1[8];
    unsigned long long z = pack2(0.f, 0.f);
    #pragma unroll
    for (int c = 0; c < 8; c++) { acc0[c] = z; acc1[c] = z; }
    #pragma unroll 8
    for (int k = 0; k < 64; k++) {
        float a0 = sS[rl][k];
        float a1 = sS[rl + 64][k];
        unsigned long long aa0 = pack2(a0, a0);
        unsigned long long aa1 = pack2(a1, a1);
        #pragma unroll
        for (int q = 0; q < 4; q++) {
            ulonglong2 w2 = *reinterpret_cast<const ulonglong2*>(&sW[k][(cg << 4) + (q << 2)]);
            FMA2(acc0[2 * q + 0], aa0, w2.x);
            FMA2(acc0[2 * q + 1], aa0, w2.y);
            FMA2(acc1[2 * q + 0], aa1, w2.x);
            FMA2(acc1[2 * q + 1], aa1, w2.y);
        }
    }
    #pragma unroll
    for (int half = 0; half < 2; half++) {
        int gr = rowBase + rl + half * 64;
        if (gr < NN) {
            unsigned long long* acc = half ? acc1 : acc0;
            #pragma unroll
            for (int q = 0; q < 4; q++) {
                float e0, e1, e2, e3;
                unpack2(acc[2 * q + 0], e0, e1);
                unpack2(acc[2 * q + 1], e2, e3);
                float4 o;
                o.x = fmaxf(e0, 0.f);
                o.y = fmaxf(e1, 0.f);
                o.z = fmaxf(e2, 0.f);
                o.w = fmaxf(e3, 0.f);
                *reinterpret_cast<float4*>(&g_h[gr * HD + (cg << 4) + (q << 2)]) = o;
            }
        }
    }
}

// ---------------- output: log_softmax(h @ W_out + b_out) ----------------
__global__ void k_out(const float* __restrict__ Wout, const float* __restrict__ bout,
                      float* __restrict__ out) {
    __shared__ float sW[HD * NCLS];
    __shared__ float sb[NCLS];
    __shared__ float srow[8][64];
    int tid = threadIdx.x;
    for (int i = tid; i < HD * NCLS; i += 256) sW[i] = Wout[i];
    if (tid < NCLS) sb[tid] = bout[tid];
    __syncthreads();
    int wid = tid >> 5, lane = tid & 31;
    int r = blockIdx.x * 8 + wid;
    if (r >= NN) return;
    srow[wid][lane]      = g_h[r * HD + lane];
    srow[wid][lane + 32] = g_h[r * HD + lane + 32];
    __syncwarp();
    int c2 = (lane & 7) + 32;
    float a0 = sb[lane];
    float a1 = sb[c2];
    #pragma unroll 8
    for (int k = 0; k < HD; k++) {
        float hk = srow[wid][k];
        a0 += hk * sW[k * NCLS + lane];
        a1 += hk * sW[k * NCLS + c2];
    }
    bool has2 = (lane < 8);
    float m = fmaxf(a0, has2 ? a1 : -INFINITY);
    #pragma unroll
    for (int o = 16; o; o >>= 1) m = fmaxf(m, __shfl_xor_sync(0xFFFFFFFFu, m, o));
    float s = __expf(a0 - m) + (has2 ? __expf(a1 - m) : 0.f);
    #pragma unroll
    for (int o = 16; o; o >>= 1) s += __shfl_xor_sync(0xFFFFFFFFu, s, o);
    float lse = m + __logf(s);
    out[r * NCLS + lane] = a0 - lse;
    if (has2) out[r * NCLS + c2] = a1 - lse;
}

// ---------------- launch ----------------
extern "C" void kernel_launch(void* const* d_in, const int* in_sizes, int n_in,
                              void* d_out, int out_size) {
    const float* x      = (const float*)d_in[0];
    const int*   row    = (const int*)  d_in[1];
    const int*   col    = (const int*)  d_in[2];
    const float* ew     = (const float*)d_in[3];
    const float* W_in   = (const float*)d_in[4];
    const float* b_in   = (const float*)d_in[5];
    const float* conv_W = (const float*)d_in[6];
    const float* W_out  = (const float*)d_in[7];
    const float* b_out  = (const float*)d_in[8];
    float* out = (float*)d_out;

    // CSR build
    k_zero_cnt<<<(NN + 255) / 256, 256>>>();
    k_count   <<<(EE + 255) / 256, 256>>>(row);
    int nb = (NN + 1023) / 1024;
    k_scan1  <<<nb, 1024>>>();
    k_scan2  <<<1, 32>>>(nb);
    k_scan3  <<<(NN + 255) / 256, 256>>>();
    k_scatter<<<(EE + 255) / 256, 256>>>(row, col, ew);

    // per-layer combined matrices
    k_make_M<<<NL, 256>>>(conv_W);

    // input projection
    k_gemm_in<<<(NN + 127) / 128, 256>>>(x, W_in, b_in);

    // 8 GCNII layers
    for (int l = 0; l < NL; l++) {
        k_spmm   <<<(NN * 16 + 255) / 256, 256>>>(l == 0 ? 1 : 0);
        k_combine<<<(NN + 127) / 128, 256>>>(l);
    }

    // output head + log_softmax
    k_out<<<(NN + 7) / 8, 256>>>(W_out, b_out, out);
}